// round 2
// baseline (speedup 1.0000x reference)
#include <cuda_runtime.h>
#include <math.h>

#define BSZ 16
#define SEQ 2048
#define HID 1024
#define NSP_PER_B 32
#define NCLS 8
#define NLBL 3
#define NSPAN (BSZ * NSP_PER_B)   // 512
#define H4 (HID / 4)              // 256

__device__ int g_ticket = 0;      // reset to 0 by the last CTA each launch

// One CTA per span: mean-pool rows [head+1, tail) of encoder over H, dot with
// W[c,:,:], add bias -> 3 logits. Last CTA to finish computes the NLL loss.
__global__ __launch_bounds__(256, 4)
void fused_kernel(const float* __restrict__ enc,
                  const float* __restrict__ W,
                  const float* __restrict__ bias,
                  const int* __restrict__ head,
                  const int* __restrict__ tail,
                  const int* __restrict__ cls,
                  const int* __restrict__ labels,
                  float* __restrict__ out,       // [NSPAN*NLBL] logits, [NSPAN*NLBL] loss
                  int write_loss)
{
    const int span = blockIdx.x;            // 0..511
    const int b    = span / NSP_PER_B;
    const int s0   = head[span] + 1;
    const int n    = tail[span] - s0;       // span length (63 here)
    const int c    = cls[span];
    const int tid  = threadIdx.x;           // 256 threads, 4 H-cols each

    const float4* base = reinterpret_cast<const float4*>(enc)
                       + ((long)b * SEQ + s0) * H4 + tid;

    float4 a0 = make_float4(0.f, 0.f, 0.f, 0.f);
    float4 a1 = a0, a2 = a0, a3 = a0;
    float4 a4 = a0, a5 = a0, a6 = a0, a7 = a0;
    int s = 0;
    for (; s + 8 <= n; s += 8) {
        float4 v0 = base[(s + 0) * H4];
        float4 v1 = base[(s + 1) * H4];
        float4 v2 = base[(s + 2) * H4];
        float4 v3 = base[(s + 3) * H4];
        float4 v4 = base[(s + 4) * H4];
        float4 v5 = base[(s + 5) * H4];
        float4 v6 = base[(s + 6) * H4];
        float4 v7 = base[(s + 7) * H4];
        a0.x += v0.x; a0.y += v0.y; a0.z += v0.z; a0.w += v0.w;
        a1.x += v1.x; a1.y += v1.y; a1.z += v1.z; a1.w += v1.w;
        a2.x += v2.x; a2.y += v2.y; a2.z += v2.z; a2.w += v2.w;
        a3.x += v3.x; a3.y += v3.y; a3.z += v3.z; a3.w += v3.w;
        a4.x += v4.x; a4.y += v4.y; a4.z += v4.z; a4.w += v4.w;
        a5.x += v5.x; a5.y += v5.y; a5.z += v5.z; a5.w += v5.w;
        a6.x += v6.x; a6.y += v6.y; a6.z += v6.z; a6.w += v6.w;
        a7.x += v7.x; a7.y += v7.y; a7.z += v7.z; a7.w += v7.w;
    }
    for (; s < n; ++s) {
        float4 v = base[s * H4];
        a0.x += v.x; a0.y += v.y; a0.z += v.z; a0.w += v.w;
    }
    float4 acc;
    acc.x = ((a0.x + a1.x) + (a2.x + a3.x)) + ((a4.x + a5.x) + (a6.x + a7.x));
    acc.y = ((a0.y + a1.y) + (a2.y + a3.y)) + ((a4.y + a5.y) + (a6.y + a7.y));
    acc.z = ((a0.z + a1.z) + (a2.z + a3.z)) + ((a4.z + a5.z) + (a6.z + a7.z));
    acc.w = ((a0.w + a1.w) + (a2.w + a3.w)) + ((a4.w + a5.w) + (a6.w + a7.w));

    // W is (C, H, L): the 4 columns this thread owns are 12 contiguous floats.
    const float4* w4 = reinterpret_cast<const float4*>(W + (long)c * HID * NLBL)
                     + tid * 3;
    float4 w0 = w4[0], w1 = w4[1], w2 = w4[2];
    // layout: h:[l0 l1 l2] h+1:[l0 l1 l2] h+2:[l0 l1 l2] h+3:[l0 l1 l2]
    float p0 = acc.x * w0.x + acc.y * w0.w + acc.z * w1.z + acc.w * w2.y;
    float p1 = acc.x * w0.y + acc.y * w1.x + acc.z * w1.w + acc.w * w2.z;
    float p2 = acc.x * w0.z + acc.y * w1.y + acc.z * w2.x + acc.w * w2.w;

    // block reduction: warp shuffle then 8-warp smem combine
    #pragma unroll
    for (int off = 16; off > 0; off >>= 1) {
        p0 += __shfl_down_sync(0xffffffffu, p0, off);
        p1 += __shfl_down_sync(0xffffffffu, p1, off);
        p2 += __shfl_down_sync(0xffffffffu, p2, off);
    }
    __shared__ float sm[3][8];
    const int warp = tid >> 5, lane = tid & 31;
    if (lane == 0) { sm[0][warp] = p0; sm[1][warp] = p1; sm[2][warp] = p2; }
    __syncthreads();

    __shared__ int s_last;
    if (tid == 0) {
        float inv = 1.0f / (float)n;
        float t0 = 0.f, t1 = 0.f, t2 = 0.f;
        #pragma unroll
        for (int w = 0; w < 8; ++w) { t0 += sm[0][w]; t1 += sm[1][w]; t2 += sm[2][w]; }
        out[span * NLBL + 0] = t0 * inv + bias[c * NLBL + 0];
        out[span * NLBL + 1] = t1 * inv + bias[c * NLBL + 1];
        out[span * NLBL + 2] = t2 * inv + bias[c * NLBL + 2];
        int last = 0;
        if (write_loss) {
            __threadfence();                     // publish logits before ticket
            int t = atomicAdd(&g_ticket, 1);
            last = (t == NSPAN - 1);
        }
        s_last = last;
    }
    __syncthreads();

    if (!s_last) return;

    // ---- last CTA: compute masked-mean NLL over all 512 spans ----
    __threadfence();   // acquire: other CTAs' logits now visible
    float nll = 0.f, vf = 0.f;
    #pragma unroll
    for (int r = 0; r < 2; ++r) {
        int i = tid + r * 256;
        float l0 = out[i * 3 + 0];
        float l1 = out[i * 3 + 1];
        float l2 = out[i * 3 + 2];
        int lab = labels[i];
        if (lab >= 0) {
            float m   = fmaxf(l0, fmaxf(l1, l2));
            float lse = m + logf(expf(l0 - m) + expf(l1 - m) + expf(l2 - m));
            float lv  = (lab == 0) ? l0 : ((lab == 1) ? l1 : l2);
            nll += lse - lv;
            vf  += 1.f;
        }
    }
    #pragma unroll
    for (int off = 16; off > 0; off >>= 1) {
        nll += __shfl_down_sync(0xffffffffu, nll, off);
        vf  += __shfl_down_sync(0xffffffffu, vf,  off);
    }
    __shared__ float sn[8], sv[8];
    if (lane == 0) { sn[warp] = nll; sv[warp] = vf; }
    __syncthreads();
    if (tid == 0) {
        float tn = 0.f, tv = 0.f;
        #pragma unroll
        for (int w = 0; w < 8; ++w) { tn += sn[w]; tv += sv[w]; }
        out[NSPAN * NLBL] = tn / tv;
        g_ticket = 0;                            // reset for next graph replay
    }
}

extern "C" void kernel_launch(void* const* d_in, const int* in_sizes, int n_in,
                              void* d_out, int out_size)
{
    const float* enc  = (const float*)d_in[0];   // (16,2048,1024)
    const float* W    = (const float*)d_in[1];   // (8,1024,3)
    const float* bias = (const float*)d_in[2];   // (8,3)
    const int*   head = (const int*)d_in[3];     // (16,32)
    const int*   tail = (const int*)d_in[4];     // (16,32)
    const int*   cls  = (const int*)d_in[5];     // (16,32)
    const int*   lab  = (const int*)d_in[6];     // (16,32)
    float* out = (float*)d_out;                  // logits (512*3) then loss

    int write_loss = (out_size > NSPAN * NLBL) ? 1 : 0;
    fused_kernel<<<NSPAN, 256>>>(enc, W, bias, head, tail, cls, lab, out, write_loss);
}